// round 7
// baseline (speedup 1.0000x reference)
#include <cuda_runtime.h>
#include <cuda_fp16.h>
#include <math_constants.h>
#include <cstdint>

// Problem constants:
//   x: [N, D] fp32,  cb: [K, D] fp32 (unit rows)
//   sims = x @ cb^T [N,K]; labels = argmax_k (first occurrence); preds = cb[labels]
#define NN 131072
#define DD 512
#define KK 2048

#define BM 128
#define BN 128
#define BK 32
#define NITERS (DD / BK)    // 16

// Fragment-layout smem (u32 words), per stage, CONSUMER-VECTORIZED:
//   A word: ((k16*8 + m16)*32 + lane)*4 + reg   -> uint4 load per fragment
//   B word: ((k16*16 + n8)*32 + lane)*2 + reg   -> uint2 load per fragment
#define AH_OFF 0
#define AL_OFF 2048
#define BH_OFF 4096
#define BL_OFF 6144
#define STAGE_U32 8192
#define SMEM_BYTES (2 * STAGE_U32 * 4)   // 65536

// Pre-split fp16 hi/lo copies of the inputs (written by split kernels).
__device__ half g_xhi[(size_t)NN * DD];
__device__ half g_xlo[(size_t)NN * DD];
__device__ half g_cbhi[(size_t)KK * DD];
__device__ half g_cblo[(size_t)KK * DD];

__device__ __forceinline__ uint32_t h2u(half2 h) {
    return *reinterpret_cast<uint32_t*>(&h);
}

// ---------------------------------------------------------------------------
// Pre-pass: split fp32 -> fp16 hi + fp16 lo (lo = rn(f - rn(f)))
// ---------------------------------------------------------------------------
__device__ __forceinline__ void split4(float4 v, uint2& hi, uint2& lo) {
    half2 h01 = __float22half2_rn(make_float2(v.x, v.y));
    half2 h23 = __float22half2_rn(make_float2(v.z, v.w));
    float2 f01 = __half22float2(h01), f23 = __half22float2(h23);
    half2 l01 = __float22half2_rn(make_float2(v.x - f01.x, v.y - f01.y));
    half2 l23 = __float22half2_rn(make_float2(v.z - f23.x, v.w - f23.y));
    hi = make_uint2(h2u(h01), h2u(h23));
    lo = make_uint2(h2u(l01), h2u(l23));
}

__global__ __launch_bounds__(256) void split_x_kernel(const float* __restrict__ src) {
    size_t i = (size_t)blockIdx.x * blockDim.x + threadIdx.x;   // one float4 each
    float4 v = ((const float4*)src)[i];
    uint2 hi, lo;
    split4(v, hi, lo);
    *(uint2*)&g_xhi[4 * i] = hi;
    *(uint2*)&g_xlo[4 * i] = lo;
}

__global__ __launch_bounds__(256) void split_cb_kernel(const float* __restrict__ src) {
    size_t i = (size_t)blockIdx.x * blockDim.x + threadIdx.x;
    float4 v = ((const float4*)src)[i];
    uint2 hi, lo;
    split4(v, hi, lo);
    *(uint2*)&g_cbhi[4 * i] = hi;
    *(uint2*)&g_cblo[4 * i] = lo;
}

__device__ __forceinline__ void mma16816(float* d, const uint32_t* a, const uint32_t* b) {
    asm volatile(
        "mma.sync.aligned.m16n8k16.row.col.f32.f16.f16.f32 "
        "{%0,%1,%2,%3}, {%4,%5,%6,%7}, {%8,%9}, {%0,%1,%2,%3};"
        : "+f"(d[0]), "+f"(d[1]), "+f"(d[2]), "+f"(d[3])
        : "r"(a[0]), "r"(a[1]), "r"(a[2]), "r"(a[3]), "r"(b[0]), "r"(b[1]));
}

// ---------------------------------------------------------------------------
// Kernel 1: fp16x3 GEMM  C[m,n] = sum_d A[m,d]*B[n,d]  (emulated fp32)
// Producer gathers pre-split halves straight into fragment layout (no math).
// ---------------------------------------------------------------------------
__global__ __launch_bounds__(256, 1)
void gemm_f16x3_kernel(float* __restrict__ C)
{
    extern __shared__ uint32_t dsm[];
    const int tid = threadIdx.x;
    const int lane = tid & 31;
    const int wid = tid >> 5;
    const int wm = wid & 1;          // 2 m-warps
    const int wn = wid >> 1;         // 4 n-warps
    const int bm = blockIdx.y * BM;
    const int bn = blockIdx.x * BN;

    // Producer mapping (consumer-identical): this thread fills, for each of
    // its groups, the 16B (A) / 8B (B) word-block of `lane`.
    const int arow = bm + wid * 16 + (lane >> 2);   // m16 = wid, rl = lane>>2
    const int akp  = lane & 3;                      // kpl low bits

    uint32_t pA[2][2][4];   // [k16][hi/lo][reg]
    uint32_t pB[4][2][2];   // [group][hi/lo][reg]

    auto prefetch = [&](int it) {
        const int kbase = it * BK;
#pragma unroll
        for (int gi = 0; gi < 2; ++gi) {            // k16 = gi
            const int k0 = kbase + (gi * 8 + akp) * 2;
            const size_t i00 = (size_t)arow * DD + k0;
            const size_t i10 = i00 + (size_t)8 * DD;
            pA[gi][0][0] = *(const uint32_t*)&g_xhi[i00];
            pA[gi][0][1] = *(const uint32_t*)&g_xhi[i10];
            pA[gi][0][2] = *(const uint32_t*)&g_xhi[i00 + 8];
            pA[gi][0][3] = *(const uint32_t*)&g_xhi[i10 + 8];
            pA[gi][1][0] = *(const uint32_t*)&g_xlo[i00];
            pA[gi][1][1] = *(const uint32_t*)&g_xlo[i10];
            pA[gi][1][2] = *(const uint32_t*)&g_xlo[i00 + 8];
            pA[gi][1][3] = *(const uint32_t*)&g_xlo[i10 + 8];
        }
#pragma unroll
        for (int gi = 0; gi < 4; ++gi) {            // group g = wid + gi*8
            const int g = wid + gi * 8;
            const int k16 = g >> 4, n8 = g & 15;
            const int brow = bn + n8 * 8 + (lane >> 2);
            const int k0 = kbase + (k16 * 8 + akp) * 2;
            const size_t i0 = (size_t)brow * DD + k0;
            pB[gi][0][0] = *(const uint32_t*)&g_cbhi[i0];
            pB[gi][0][1] = *(const uint32_t*)&g_cbhi[i0 + 8];
            pB[gi][1][0] = *(const uint32_t*)&g_cblo[i0];
            pB[gi][1][1] = *(const uint32_t*)&g_cblo[i0 + 8];
        }
    };
    auto store_stage = [&](uint32_t* S) {
#pragma unroll
        for (int gi = 0; gi < 2; ++gi) {
            const int g = wid + gi * 8;             // g = k16*8 + m16
            *(uint4*)&S[AH_OFF + (g * 32 + lane) * 4] = *(uint4*)pA[gi][0];
            *(uint4*)&S[AL_OFF + (g * 32 + lane) * 4] = *(uint4*)pA[gi][1];
        }
#pragma unroll
        for (int gi = 0; gi < 4; ++gi) {
            const int g = wid + gi * 8;
            *(uint2*)&S[BH_OFF + (g * 32 + lane) * 2] = *(uint2*)pB[gi][0];
            *(uint2*)&S[BL_OFF + (g * 32 + lane) * 2] = *(uint2*)pB[gi][1];
        }
    };

    float acc[4][4][4];
#pragma unroll
    for (int i = 0; i < 4; ++i)
#pragma unroll
        for (int j = 0; j < 4; ++j)
#pragma unroll
            for (int r = 0; r < 4; ++r) acc[i][j][r] = 0.0f;

    prefetch(0);
    store_stage(dsm);            // stage 0
    __syncthreads();

#pragma unroll 1
    for (int it = 0; it < NITERS; ++it) {
        uint32_t* S = dsm + (it & 1) * STAGE_U32;
        uint32_t* Snxt = dsm + ((it & 1) ^ 1) * STAGE_U32;

        if (it + 1 < NITERS) prefetch(it + 1);

#pragma unroll
        for (int s = 0; s < 2; ++s) {
            uint32_t ah[4][4], al[4][4], bh[4][2], bl[4][2];
            // hi fragments (vectorized: uint4 for A, uint2 for B)
#pragma unroll
            for (int i = 0; i < 4; ++i)
                *(uint4*)ah[i] = *(const uint4*)&S[AH_OFF + ((s * 8 + wm * 4 + i) * 32 + lane) * 4];
#pragma unroll
            for (int j = 0; j < 4; ++j)
                *(uint2*)bh[j] = *(const uint2*)&S[BH_OFF + ((s * 16 + wn * 4 + j) * 32 + lane) * 2];
            // pass 1: hi*hi
#pragma unroll
            for (int i = 0; i < 4; ++i)
#pragma unroll
                for (int j = 0; j < 4; ++j) mma16816(acc[i][j], ah[i], bh[j]);
            // lo-B fragments, pass 2: hi*lo
#pragma unroll
            for (int j = 0; j < 4; ++j)
                *(uint2*)bl[j] = *(const uint2*)&S[BL_OFF + ((s * 16 + wn * 4 + j) * 32 + lane) * 2];
#pragma unroll
            for (int i = 0; i < 4; ++i)
#pragma unroll
                for (int j = 0; j < 4; ++j) mma16816(acc[i][j], ah[i], bl[j]);
            // lo-A fragments, pass 3: lo*hi
#pragma unroll
            for (int i = 0; i < 4; ++i)
                *(uint4*)al[i] = *(const uint4*)&S[AL_OFF + ((s * 8 + wm * 4 + i) * 32 + lane) * 4];
#pragma unroll
            for (int i = 0; i < 4; ++i)
#pragma unroll
                for (int j = 0; j < 4; ++j) mma16816(acc[i][j], al[i], bh[j]);
        }

        if (it + 1 < NITERS) store_stage(Snxt);
        __syncthreads();
    }

    // epilogue: c-frag direct STG (adjacent col pairs -> float2)
#pragma unroll
    for (int i = 0; i < 4; ++i) {
        int r0 = bm + wm * 64 + i * 16 + (lane >> 2);
#pragma unroll
        for (int j = 0; j < 4; ++j) {
            int c = bn + wn * 32 + j * 8 + (lane & 3) * 2;
            *(float2*)&C[(size_t)r0 * KK + c] = make_float2(acc[i][j][0], acc[i][j][1]);
            *(float2*)&C[(size_t)(r0 + 8) * KK + c] = make_float2(acc[i][j][2], acc[i][j][3]);
        }
    }
}

// ---------------------------------------------------------------------------
// Kernel 2: per-row argmax via block-max + equality match (cheap, ILP-friendly)
// with near-tie sequential-fp32 fixup (bitwise-faithful to the exact kernel)
// and fused codebook gather.
// ---------------------------------------------------------------------------
#define MARGIN 3e-4f

__device__ __forceinline__ void merge1(float& v1, int& i1, float ov, int oi) {
    if (ov > v1 || (ov == v1 && oi < i1)) { v1 = ov; i1 = oi; }
}

__global__ __launch_bounds__(256)
void argmax_gather_kernel(const float* __restrict__ sims,
                          const float* __restrict__ cb,
                          const float* __restrict__ x,
                          float* __restrict__ preds,
                          void* __restrict__ labels,
                          int labels_are_i64)
{
    const int n = blockIdx.x;
    const int tid = threadIdx.x;
    const int lane = tid & 31, warp = tid >> 5;
    const float4* row = (const float4*)(sims + (size_t)n * KK);

    float4 va = row[tid];
    float4 vb = row[tid + 256];
    float v[8] = {va.x, va.y, va.z, va.w, vb.x, vb.y, vb.z, vb.w};

    // --- block max (tree, full ILP) ---
    float m = fmaxf(fmaxf(fmaxf(v[0], v[1]), fmaxf(v[2], v[3])),
                    fmaxf(fmaxf(v[4], v[5]), fmaxf(v[6], v[7])));
#pragma unroll
    for (int off = 16; off > 0; off >>= 1)
        m = fmaxf(m, __shfl_xor_sync(0xFFFFFFFFu, m, off));

    __shared__ float swm[8];
    __shared__ int   swi[8], swc[8];
    __shared__ int   s_final;
    __shared__ float s_exact[2];
    if (lane == 0) swm[warp] = m;
    __syncthreads();
    float bv = swm[0];
#pragma unroll
    for (int w = 1; w < 8; ++w) bv = fmaxf(bv, swm[w]);

    // --- index of first occurrence + near-tie count ---
    int myidx = 0x7FFFFFFF;
    int cnt = 0;
    const float thr = bv - MARGIN;
#pragma unroll
    for (int e = 0; e < 8; ++e) {
        int g = (e < 4) ? tid * 4 + e : (tid + 256) * 4 + (e - 4);
        if (v[e] == bv) myidx = min(myidx, g);
        cnt += (v[e] > thr) ? 1 : 0;
    }
#pragma unroll
    for (int off = 16; off > 0; off >>= 1) {
        myidx = min(myidx, __shfl_xor_sync(0xFFFFFFFFu, myidx, off));
        cnt  +=            __shfl_xor_sync(0xFFFFFFFFu, cnt,  off);
    }
    if (lane == 0) { swi[warp] = myidx; swc[warp] = cnt; }
    __syncthreads();
    int bidx = swi[0], bcnt = swc[0];
#pragma unroll
    for (int w = 1; w < 8; ++w) { bidx = min(bidx, swi[w]); bcnt += swc[w]; }

    int final_idx = bidx;

    if (bcnt > 1) {
        // --- rare path: find runner-up, then exact sequential-fp32 decision ---
        float v2 = -CUDART_INF_F;
        int i2 = 0x7FFFFFFF;
#pragma unroll
        for (int e = 0; e < 8; ++e) {
            int g = (e < 4) ? tid * 4 + e : (tid + 256) * 4 + (e - 4);
            if (g != bidx) merge1(v2, i2, v[e], g);
        }
#pragma unroll
        for (int off = 16; off > 0; off >>= 1) {
            float ov = __shfl_xor_sync(0xFFFFFFFFu, v2, off);
            int   oi = __shfl_xor_sync(0xFFFFFFFFu, i2, off);
            merge1(v2, i2, ov, oi);
        }
        if (lane == 0) { swm[warp] = v2; swi[warp] = i2; }
        __syncthreads();
        float fv2 = swm[0]; int fi2 = swi[0];
#pragma unroll
        for (int w = 1; w < 8; ++w) merge1(fv2, fi2, swm[w], swi[w]);

        // Exact fixup: replicate the exact-fp32 kernel's sequential fmaf chain
        // bitwise (its tie decisions matched the reference with rel_err 0.0).
        __shared__ float sx[DD], sc1[DD], sc2[DD];
        const int a = bidx, b = fi2;
        for (int d = tid; d < DD; d += 256) {
            sx[d]  = x[(size_t)n * DD + d];
            sc1[d] = cb[(size_t)a * DD + d];
            sc2[d] = cb[(size_t)b * DD + d];
        }
        __syncthreads();
        if (tid < 2) {
            const float* cr = tid ? sc2 : sc1;
            float s = 0.0f;
#pragma unroll 8
            for (int d = 0; d < DD; ++d) s = fmaf(sx[d], cr[d], s);
            s_exact[tid] = s;
        }
        __syncthreads();
        if (tid == 0) {
            const float sA = s_exact[0], sB = s_exact[1];
            int fin;
            if (sA > sB)      fin = a;
            else if (sB > sA) fin = b;
            else              fin = (a < b) ? a : b;
            s_final = fin;
        }
        __syncthreads();
        final_idx = s_final;
    }

    const int lbl = final_idx;
    if (tid == 0) {
        if (labels_are_i64) ((long long*)labels)[n] = (long long)lbl;
        else                ((float*)labels)[n] = (float)lbl;
    }
    if (tid < 128) {
        float4 c = ((const float4*)(cb + (size_t)lbl * DD))[tid];
        ((float4*)(preds + (size_t)n * DD))[tid] = c;
    }
}

// ---------------------------------------------------------------------------
// Launch
// ---------------------------------------------------------------------------
extern "C" void kernel_launch(void* const* d_in, const int* in_sizes, int n_in,
                              void* d_out, int out_size)
{
    const float* x  = (const float*)d_in[0];   // [N, D]
    const float* cb = (const float*)d_in[1];   // [K, D]

    float* out = (float*)d_out;
    const size_t predsSz = (size_t)NN * DD;
    const size_t simsSz  = (size_t)NN * KK;

    size_t labelElems;
    int labels_are_i64;
    if ((size_t)(unsigned)out_size == predsSz + 2 * (size_t)NN + simsSz) {
        labelElems = 2 * (size_t)NN; labels_are_i64 = 1;
    } else {
        labelElems = (size_t)NN;     labels_are_i64 = 0;
    }

    float* preds  = out;
    void*  labels = (void*)(out + predsSz);
    float* sims   = out + predsSz + labelElems;

    static int attr_set = 0;
    if (!attr_set) {
        cudaFuncSetAttribute(gemm_f16x3_kernel,
                             cudaFuncAttributeMaxDynamicSharedMemorySize, SMEM_BYTES);
        attr_set = 1;
    }

    split_x_kernel<<<(NN * DD / 4) / 256, 256>>>(x);
    split_cb_kernel<<<(KK * DD / 4) / 256, 256>>>(cb);

    dim3 grid(KK / BN, NN / BM);   // (16, 1024)
    gemm_f16x3_kernel<<<grid, 256, SMEM_BYTES>>>(sims);
    argmax_gather_kernel<<<NN, 256>>>(sims, cb, x, preds, labels, labels_are_i64);
}

// round 8
// speedup vs baseline: 1.2694x; 1.2694x over previous
#include <cuda_runtime.h>
#include <cuda_fp16.h>
#include <math_constants.h>
#include <cstdint>

// Problem constants:
//   x: [N, D] fp32,  cb: [K, D] fp32 (unit rows)
//   sims = x @ cb^T [N,K]; labels = argmax_k (first occurrence); preds = cb[labels]
#define NN 131072
#define DD 512
#define KK 2048

#define BM 128
#define BN 128
#define BK 32
#define NITERS (DD / BK)    // 16

// Fragment-layout smem (u32 words), per stage, CONSUMER-VECTORIZED:
//   A word: ((k16*8 + m16)*32 + lane)*4 + reg   -> uint4 load per fragment
//   B word: ((k16*16 + n8)*32 + lane)*2 + reg   -> uint2 load per fragment
#define AH_OFF 0
#define AL_OFF 2048
#define BH_OFF 4096
#define BL_OFF 6144
#define STAGE_U32 8192
#define SMEM_BYTES (2 * STAGE_U32 * 4)   // 65536 (x2 blocks/SM = 128KB < 228KB)

__device__ __forceinline__ uint32_t h2u(half2 h) {
    return *reinterpret_cast<uint32_t*>(&h);
}

// word index for A element (row in [0,128), kp = k/2 in [0,16))
__device__ __forceinline__ int a_widx(int row, int kp) {
    int k16 = kp >> 3, kpl = kp & 7;
    int m16 = row >> 4, rl = row & 15;
    int reg = (rl >> 3) + ((kpl >> 2) << 1);
    int lane = ((rl & 7) << 2) + (kpl & 3);
    return (((k16 << 3) + m16) * 32 + lane) * 4 + reg;
}
// word index for B element (n in [0,128), kp in [0,16))
__device__ __forceinline__ int b_widx(int n, int kp) {
    int k16 = kp >> 3, kpl = kp & 7;
    int n8 = n >> 3, nl = n & 7;
    int reg = kpl >> 2;
    int lane = (nl << 2) + (kpl & 3);
    return (((k16 << 4) + n8) * 32 + lane) * 2 + reg;
}

__device__ __forceinline__ void mma16816(float* d, const uint32_t* a, const uint32_t* b) {
    asm volatile(
        "mma.sync.aligned.m16n8k16.row.col.f32.f16.f16.f32 "
        "{%0,%1,%2,%3}, {%4,%5,%6,%7}, {%8,%9}, {%0,%1,%2,%3};"
        : "+f"(d[0]), "+f"(d[1]), "+f"(d[2]), "+f"(d[3])
        : "r"(a[0]), "r"(a[1]), "r"(a[2]), "r"(a[3]), "r"(b[0]), "r"(b[1]));
}

// ---------------------------------------------------------------------------
// Kernel 1: fp16x3 GEMM  C[m,n] = sum_d A[m,d]*B[n,d]  (emulated fp32)
// occ=2 for cross-block latency hiding of the per-iter sync/LDS bubbles.
// ---------------------------------------------------------------------------
__global__ __launch_bounds__(256, 2)
void gemm_f16x3_kernel(const float* __restrict__ A,
                       const float* __restrict__ B,
                       float* __restrict__ C)
{
    extern __shared__ uint32_t dsm[];
    const int tid = threadIdx.x;
    const int lane = tid & 31;
    const int wid = tid >> 5;
    const int wm = wid & 1;          // 2 m-warps
    const int wn = wid >> 1;         // 4 n-warps
    const int bm = blockIdx.y * BM;
    const int bn = blockIdx.x * BN;

    // per-thread global-load coordinates (4 float4 per operand per tile)
    int rowA[4], f4A[4];
#pragma unroll
    for (int j = 0; j < 4; ++j) {
        int q = j * 256 + tid;
        rowA[j] = q >> 3;
        f4A[j] = q & 7;
    }

    float4 pa[4], pb[4];
    auto prefetch = [&](int it) {
        const int kk = it * BK;
#pragma unroll
        for (int j = 0; j < 4; ++j) {
            pa[j] = *(const float4*)(A + (size_t)(bm + rowA[j]) * DD + kk + f4A[j] * 4);
            pb[j] = *(const float4*)(B + (size_t)(bn + rowA[j]) * DD + kk + f4A[j] * 4);
        }
    };
    auto store_stage = [&](uint32_t* S) {
#pragma unroll
        for (int j = 0; j < 4; ++j) {
            // A
            {
                float4 v = pa[j];
                half2 h01 = __float22half2_rn(make_float2(v.x, v.y));
                half2 h23 = __float22half2_rn(make_float2(v.z, v.w));
                float2 f01 = __half22float2(h01), f23 = __half22float2(h23);
                half2 l01 = __float22half2_rn(make_float2(v.x - f01.x, v.y - f01.y));
                half2 l23 = __float22half2_rn(make_float2(v.z - f23.x, v.w - f23.y));
                int i0 = a_widx(rowA[j], 2 * f4A[j]);   // kp and kp+1 -> i0, i0+4
                S[AH_OFF + i0]     = h2u(h01);
                S[AH_OFF + i0 + 4] = h2u(h23);
                S[AL_OFF + i0]     = h2u(l01);
                S[AL_OFF + i0 + 4] = h2u(l23);
            }
            // B
            {
                float4 v = pb[j];
                half2 h01 = __float22half2_rn(make_float2(v.x, v.y));
                half2 h23 = __float22half2_rn(make_float2(v.z, v.w));
                float2 f01 = __half22float2(h01), f23 = __half22float2(h23);
                half2 l01 = __float22half2_rn(make_float2(v.x - f01.x, v.y - f01.y));
                half2 l23 = __float22half2_rn(make_float2(v.z - f23.x, v.w - f23.y));
                int i0 = b_widx(rowA[j], 2 * f4A[j]);   // kp and kp+1 -> i0, i0+2
                S[BH_OFF + i0]     = h2u(h01);
                S[BH_OFF + i0 + 2] = h2u(h23);
                S[BL_OFF + i0]     = h2u(l01);
                S[BL_OFF + i0 + 2] = h2u(l23);
            }
        }
    };

    float acc[4][4][4];
#pragma unroll
    for (int i = 0; i < 4; ++i)
#pragma unroll
        for (int j = 0; j < 4; ++j)
#pragma unroll
            for (int r = 0; r < 4; ++r) acc[i][j][r] = 0.0f;

    prefetch(0);
    store_stage(dsm);            // stage 0
    __syncthreads();

#pragma unroll 1
    for (int it = 0; it < NITERS; ++it) {
        uint32_t* S = dsm + (it & 1) * STAGE_U32;
        uint32_t* Snxt = dsm + ((it & 1) ^ 1) * STAGE_U32;

        if (it + 1 < NITERS) prefetch(it + 1);

#pragma unroll
        for (int s = 0; s < 2; ++s) {
            uint32_t ah[4][4], al[4][4], bh[4][2], bl[4][2];
            // hi fragments (vectorized: uint4 for A, uint2 for B)
#pragma unroll
            for (int i = 0; i < 4; ++i)
                *(uint4*)ah[i] = *(const uint4*)&S[AH_OFF + ((s * 8 + wm * 4 + i) * 32 + lane) * 4];
#pragma unroll
            for (int j = 0; j < 4; ++j)
                *(uint2*)bh[j] = *(const uint2*)&S[BH_OFF + ((s * 16 + wn * 4 + j) * 32 + lane) * 2];
            // pass 1: hi*hi
#pragma unroll
            for (int i = 0; i < 4; ++i)
#pragma unroll
                for (int j = 0; j < 4; ++j) mma16816(acc[i][j], ah[i], bh[j]);
            // lo-B fragments, pass 2: hi*lo
#pragma unroll
            for (int j = 0; j < 4; ++j)
                *(uint2*)bl[j] = *(const uint2*)&S[BL_OFF + ((s * 16 + wn * 4 + j) * 32 + lane) * 2];
#pragma unroll
            for (int i = 0; i < 4; ++i)
#pragma unroll
                for (int j = 0; j < 4; ++j) mma16816(acc[i][j], ah[i], bl[j]);
            // lo-A fragments, pass 3: lo*hi
#pragma unroll
            for (int i = 0; i < 4; ++i)
                *(uint4*)al[i] = *(const uint4*)&S[AL_OFF + ((s * 8 + wm * 4 + i) * 32 + lane) * 4];
#pragma unroll
            for (int i = 0; i < 4; ++i)
#pragma unroll
                for (int j = 0; j < 4; ++j) mma16816(acc[i][j], al[i], bh[j]);
        }

        if (it + 1 < NITERS) store_stage(Snxt);
        __syncthreads();
    }

    // epilogue: c-frag direct STG (adjacent col pairs -> float2)
#pragma unroll
    for (int i = 0; i < 4; ++i) {
        int r0 = bm + wm * 64 + i * 16 + (lane >> 2);
#pragma unroll
        for (int j = 0; j < 4; ++j) {
            int c = bn + wn * 32 + j * 8 + (lane & 3) * 2;
            *(float2*)&C[(size_t)r0 * KK + c] = make_float2(acc[i][j][0], acc[i][j][1]);
            *(float2*)&C[(size_t)(r0 + 8) * KK + c] = make_float2(acc[i][j][2], acc[i][j][3]);
        }
    }
}

// ---------------------------------------------------------------------------
// Kernel 2: per-row argmax via block-max + equality match (cheap, ILP-friendly)
// with near-tie sequential-fp32 fixup (bitwise-faithful to the exact kernel)
// and fused codebook gather.
// ---------------------------------------------------------------------------
#define MARGIN 3e-4f

__device__ __forceinline__ void merge1(float& v1, int& i1, float ov, int oi) {
    if (ov > v1 || (ov == v1 && oi < i1)) { v1 = ov; i1 = oi; }
}

__global__ __launch_bounds__(256)
void argmax_gather_kernel(const float* __restrict__ sims,
                          const float* __restrict__ cb,
                          const float* __restrict__ x,
                          float* __restrict__ preds,
                          void* __restrict__ labels,
                          int labels_are_i64)
{
    const int n = blockIdx.x;
    const int tid = threadIdx.x;
    const int lane = tid & 31, warp = tid >> 5;
    const float4* row = (const float4*)(sims + (size_t)n * KK);

    float4 va = row[tid];
    float4 vb = row[tid + 256];
    float v[8] = {va.x, va.y, va.z, va.w, vb.x, vb.y, vb.z, vb.w};

    // --- block max (tree, full ILP) ---
    float m = fmaxf(fmaxf(fmaxf(v[0], v[1]), fmaxf(v[2], v[3])),
                    fmaxf(fmaxf(v[4], v[5]), fmaxf(v[6], v[7])));
#pragma unroll
    for (int off = 16; off > 0; off >>= 1)
        m = fmaxf(m, __shfl_xor_sync(0xFFFFFFFFu, m, off));

    __shared__ float swm[8];
    __shared__ int   swi[8], swc[8];
    __shared__ int   s_final;
    __shared__ float s_exact[2];
    if (lane == 0) swm[warp] = m;
    __syncthreads();
    float bv = swm[0];
#pragma unroll
    for (int w = 1; w < 8; ++w) bv = fmaxf(bv, swm[w]);

    // --- index of first occurrence + near-tie count ---
    int myidx = 0x7FFFFFFF;
    int cnt = 0;
    const float thr = bv - MARGIN;
#pragma unroll
    for (int e = 0; e < 8; ++e) {
        int g = (e < 4) ? tid * 4 + e : (tid + 256) * 4 + (e - 4);
        if (v[e] == bv) myidx = min(myidx, g);
        cnt += (v[e] > thr) ? 1 : 0;
    }
#pragma unroll
    for (int off = 16; off > 0; off >>= 1) {
        myidx = min(myidx, __shfl_xor_sync(0xFFFFFFFFu, myidx, off));
        cnt  +=            __shfl_xor_sync(0xFFFFFFFFu, cnt,  off);
    }
    if (lane == 0) { swi[warp] = myidx; swc[warp] = cnt; }
    __syncthreads();
    int bidx = swi[0], bcnt = swc[0];
#pragma unroll
    for (int w = 1; w < 8; ++w) { bidx = min(bidx, swi[w]); bcnt += swc[w]; }

    int final_idx = bidx;

    if (bcnt > 1) {
        // --- rare path: find runner-up, then exact sequential-fp32 decision ---
        float v2 = -CUDART_INF_F;
        int i2 = 0x7FFFFFFF;
#pragma unroll
        for (int e = 0; e < 8; ++e) {
            int g = (e < 4) ? tid * 4 + e : (tid + 256) * 4 + (e - 4);
            if (g != bidx) merge1(v2, i2, v[e], g);
        }
#pragma unroll
        for (int off = 16; off > 0; off >>= 1) {
            float ov = __shfl_xor_sync(0xFFFFFFFFu, v2, off);
            int   oi = __shfl_xor_sync(0xFFFFFFFFu, i2, off);
            merge1(v2, i2, ov, oi);
        }
        if (lane == 0) { swm[warp] = v2; swi[warp] = i2; }
        __syncthreads();
        float fv2 = swm[0]; int fi2 = swi[0];
#pragma unroll
        for (int w = 1; w < 8; ++w) merge1(fv2, fi2, swm[w], swi[w]);

        // Exact fixup: replicate the exact-fp32 kernel's sequential fmaf chain
        // bitwise (its tie decisions matched the reference with rel_err 0.0).
        __shared__ float sx[DD], sc1[DD], sc2[DD];
        const int a = bidx, b = fi2;
        for (int d = tid; d < DD; d += 256) {
            sx[d]  = x[(size_t)n * DD + d];
            sc1[d] = cb[(size_t)a * DD + d];
            sc2[d] = cb[(size_t)b * DD + d];
        }
        __syncthreads();
        if (tid < 2) {
            const float* cr = tid ? sc2 : sc1;
            float s = 0.0f;
#pragma unroll 8
            for (int d = 0; d < DD; ++d) s = fmaf(sx[d], cr[d], s);
            s_exact[tid] = s;
        }
        __syncthreads();
        if (tid == 0) {
            const float sA = s_exact[0], sB = s_exact[1];
            int fin;
            if (sA > sB)      fin = a;
            else if (sB > sA) fin = b;
            else              fin = (a < b) ? a : b;
            s_final = fin;
        }
        __syncthreads();
        final_idx = s_final;
    }

    const int lbl = final_idx;
    if (tid == 0) {
        if (labels_are_i64) ((long long*)labels)[n] = (long long)lbl;
        else                ((float*)labels)[n] = (float)lbl;
    }
    if (tid < 128) {
        float4 c = ((const float4*)(cb + (size_t)lbl * DD))[tid];
        ((float4*)(preds + (size_t)n * DD))[tid] = c;
    }
}

// ---------------------------------------------------------------------------
// Launch
// ---------------------------------------------------------------------------
extern "C" void kernel_launch(void* const* d_in, const int* in_sizes, int n_in,
                              void* d_out, int out_size)
{
    const float* x  = (const float*)d_in[0];   // [N, D]
    const float* cb = (const float*)d_in[1];   // [K, D]

    float* out = (float*)d_out;
    const size_t predsSz = (size_t)NN * DD;
    const size_t simsSz  = (size_t)NN * KK;

    size_t labelElems;
    int labels_are_i64;
    if ((size_t)(unsigned)out_size == predsSz + 2 * (size_t)NN + simsSz) {
        labelElems = 2 * (size_t)NN; labels_are_i64 = 1;
    } else {
        labelElems = (size_t)NN;     labels_are_i64 = 0;
    }

    float* preds  = out;
    void*  labels = (void*)(out + predsSz);
    float* sims   = out + predsSz + labelElems;

    static int attr_set = 0;
    if (!attr_set) {
        cudaFuncSetAttribute(gemm_f16x3_kernel,
                             cudaFuncAttributeMaxDynamicSharedMemorySize, SMEM_BYTES);
        attr_set = 1;
    }

    dim3 grid(KK / BN, NN / BM);   // (16, 1024)
    gemm_f16x3_kernel<<<grid, 256, SMEM_BYTES>>>(x, cb, sims);
    argmax_gather_kernel<<<NN, 256>>>(sims, cb, x, preds, labels, labels_are_i64);
}

// round 9
// speedup vs baseline: 1.6818x; 1.3249x over previous
#include <cuda_runtime.h>
#include <cuda_fp16.h>
#include <math_constants.h>
#include <cstdint>

// Problem constants:
//   x: [N, D] fp32,  cb: [K, D] fp32 (unit rows)
//   sims = x @ cb^T [N,K]; labels = argmax_k (first occurrence); preds = cb[labels]
#define NN 131072
#define DD 512
#define KK 2048

#define BM 128
#define BN 128
#define BK 32
#define NITERS (DD / BK)    // 16

// Fragment-layout smem (u32 words), per stage, CONSUMER-VECTORIZED:
//   A-hi word: ((k16*8 + m16)*32 + lane)*4 + reg   -> uint4 load per fragment
//   B word:    ((k16*16 + n8)*32 + lane)*2 + reg   -> uint2 load per fragment
#define AH_OFF 0
#define BH_OFF 2048
#define BL_OFF 4096
#define STAGE_U32 6144
#define SMEM_BYTES (2 * STAGE_U32 * 4)   // 49152

__device__ __forceinline__ uint32_t h2u(half2 h) {
    return *reinterpret_cast<uint32_t*>(&h);
}

// word index for A element (row in [0,128), kp = k/2 in [0,16))
__device__ __forceinline__ int a_widx(int row, int kp) {
    int k16 = kp >> 3, kpl = kp & 7;
    int m16 = row >> 4, rl = row & 15;
    int reg = (rl >> 3) + ((kpl >> 2) << 1);
    int lane = ((rl & 7) << 2) + (kpl & 3);
    return (((k16 << 3) + m16) * 32 + lane) * 4 + reg;
}
// word index for B element (n in [0,128), kp in [0,16))
__device__ __forceinline__ int b_widx(int n, int kp) {
    int k16 = kp >> 3, kpl = kp & 7;
    int n8 = n >> 3, nl = n & 7;
    int reg = kpl >> 2;
    int lane = (nl << 2) + (kpl & 3);
    return (((k16 << 4) + n8) * 32 + lane) * 2 + reg;
}

__device__ __forceinline__ void mma16816(float* d, const uint32_t* a, const uint32_t* b) {
    asm volatile(
        "mma.sync.aligned.m16n8k16.row.col.f32.f16.f16.f32 "
        "{%0,%1,%2,%3}, {%4,%5,%6,%7}, {%8,%9}, {%0,%1,%2,%3};"
        : "+f"(d[0]), "+f"(d[1]), "+f"(d[2]), "+f"(d[3])
        : "r"(a[0]), "r"(a[1]), "r"(a[2]), "r"(a[3]), "r"(b[0]), "r"(b[1]));
}

// ---------------------------------------------------------------------------
// Kernel 1: fp16x2 GEMM  C[m,n] = sum_d rn16(A[m,d]) * B[n,d]  (~22-bit B)
// Two passes: ah*bh + ah*bl. Error = al*b ~ 2.8e-4 rms per sim.
// ---------------------------------------------------------------------------
__global__ __launch_bounds__(256, 1)
void gemm_f16x2_kernel(const float* __restrict__ A,
                       const float* __restrict__ B,
                       float* __restrict__ C)
{
    extern __shared__ uint32_t dsm[];
    const int tid = threadIdx.x;
    const int lane = tid & 31;
    const int wid = tid >> 5;
    const int wm = wid & 1;          // 2 m-warps
    const int wn = wid >> 1;         // 4 n-warps
    const int bm = blockIdx.y * BM;
    const int bn = blockIdx.x * BN;

    // per-thread global-load coordinates (4 float4 per operand per tile)
    int rowA[4], f4A[4];
#pragma unroll
    for (int j = 0; j < 4; ++j) {
        int q = j * 256 + tid;
        rowA[j] = q >> 3;
        f4A[j] = q & 7;
    }

    float4 pa[4], pb[4];
    auto prefetch = [&](int it) {
        const int kk = it * BK;
#pragma unroll
        for (int j = 0; j < 4; ++j) {
            pa[j] = *(const float4*)(A + (size_t)(bm + rowA[j]) * DD + kk + f4A[j] * 4);
            pb[j] = *(const float4*)(B + (size_t)(bn + rowA[j]) * DD + kk + f4A[j] * 4);
        }
    };
    auto store_stage = [&](uint32_t* S) {
#pragma unroll
        for (int j = 0; j < 4; ++j) {
            // A: hi only
            {
                float4 v = pa[j];
                half2 h01 = __float22half2_rn(make_float2(v.x, v.y));
                half2 h23 = __float22half2_rn(make_float2(v.z, v.w));
                int i0 = a_widx(rowA[j], 2 * f4A[j]);   // kp and kp+1 -> i0, i0+4
                S[AH_OFF + i0]     = h2u(h01);
                S[AH_OFF + i0 + 4] = h2u(h23);
            }
            // B: hi + lo
            {
                float4 v = pb[j];
                half2 h01 = __float22half2_rn(make_float2(v.x, v.y));
                half2 h23 = __float22half2_rn(make_float2(v.z, v.w));
                float2 f01 = __half22float2(h01), f23 = __half22float2(h23);
                half2 l01 = __float22half2_rn(make_float2(v.x - f01.x, v.y - f01.y));
                half2 l23 = __float22half2_rn(make_float2(v.z - f23.x, v.w - f23.y));
                int i0 = b_widx(rowA[j], 2 * f4A[j]);   // kp and kp+1 -> i0, i0+2
                S[BH_OFF + i0]     = h2u(h01);
                S[BH_OFF + i0 + 2] = h2u(h23);
                S[BL_OFF + i0]     = h2u(l01);
                S[BL_OFF + i0 + 2] = h2u(l23);
            }
        }
    };

    float acc[4][4][4];
#pragma unroll
    for (int i = 0; i < 4; ++i)
#pragma unroll
        for (int j = 0; j < 4; ++j)
#pragma unroll
            for (int r = 0; r < 4; ++r) acc[i][j][r] = 0.0f;

    prefetch(0);
    store_stage(dsm);            // stage 0
    __syncthreads();

#pragma unroll 1
    for (int it = 0; it < NITERS; ++it) {
        uint32_t* S = dsm + (it & 1) * STAGE_U32;
        uint32_t* Snxt = dsm + ((it & 1) ^ 1) * STAGE_U32;

        if (it + 1 < NITERS) prefetch(it + 1);

#pragma unroll
        for (int s = 0; s < 2; ++s) {
            uint32_t ah[4][4], bh[4][2], bl[4][2];
#pragma unroll
            for (int i = 0; i < 4; ++i)
                *(uint4*)ah[i] = *(const uint4*)&S[AH_OFF + ((s * 8 + wm * 4 + i) * 32 + lane) * 4];
#pragma unroll
            for (int j = 0; j < 4; ++j)
                *(uint2*)bh[j] = *(const uint2*)&S[BH_OFF + ((s * 16 + wn * 4 + j) * 32 + lane) * 2];
            // pass 1: ah*bh
#pragma unroll
            for (int i = 0; i < 4; ++i)
#pragma unroll
                for (int j = 0; j < 4; ++j) mma16816(acc[i][j], ah[i], bh[j]);
            // pass 2: ah*bl
#pragma unroll
            for (int j = 0; j < 4; ++j)
                *(uint2*)bl[j] = *(const uint2*)&S[BL_OFF + ((s * 16 + wn * 4 + j) * 32 + lane) * 2];
#pragma unroll
            for (int i = 0; i < 4; ++i)
#pragma unroll
                for (int j = 0; j < 4; ++j) mma16816(acc[i][j], ah[i], bl[j]);
        }

        if (it + 1 < NITERS) store_stage(Snxt);
        __syncthreads();
    }

    // epilogue: c-frag direct STG (adjacent col pairs -> float2)
#pragma unroll
    for (int i = 0; i < 4; ++i) {
        int r0 = bm + wm * 64 + i * 16 + (lane >> 2);
#pragma unroll
        for (int j = 0; j < 4; ++j) {
            int c = bn + wn * 32 + j * 8 + (lane & 3) * 2;
            *(float2*)&C[(size_t)r0 * KK + c] = make_float2(acc[i][j][0], acc[i][j][1]);
            *(float2*)&C[(size_t)(r0 + 8) * KK + c] = make_float2(acc[i][j][2], acc[i][j][3]);
        }
    }
}

// ---------------------------------------------------------------------------
// Kernel 2: per-row argmax via block-max + equality match, with a
// candidate-set exact fixup: all indices within MARGIN of the noisy max are
// re-scored with the bitwise-faithful sequential-fp32 fmaf chain (matches the
// exact-fp32 kernel whose labels scored rel_err 0.0). MARGIN covers 2x the
// max sims noise (~1.5e-3), so the true argmax is provably in the set.
// ---------------------------------------------------------------------------
#define MARGIN 5e-3f
#define MAXCAND 8

__global__ __launch_bounds__(256)
void argmax_gather_kernel(const float* __restrict__ sims,
                          const float* __restrict__ cb,
                          const float* __restrict__ x,
                          float* __restrict__ preds,
                          void* __restrict__ labels,
                          int labels_are_i64)
{
    const int n = blockIdx.x;
    const int tid = threadIdx.x;
    const int lane = tid & 31, warp = tid >> 5;
    const float4* row = (const float4*)(sims + (size_t)n * KK);

    float4 va = row[tid];
    float4 vb = row[tid + 256];
    float v[8] = {va.x, va.y, va.z, va.w, vb.x, vb.y, vb.z, vb.w};

    // --- block max (tree, full ILP) ---
    float m = fmaxf(fmaxf(fmaxf(v[0], v[1]), fmaxf(v[2], v[3])),
                    fmaxf(fmaxf(v[4], v[5]), fmaxf(v[6], v[7])));
#pragma unroll
    for (int off = 16; off > 0; off >>= 1)
        m = fmaxf(m, __shfl_xor_sync(0xFFFFFFFFu, m, off));

    __shared__ float swm[8];
    __shared__ int   swi[8], swc[8];
    __shared__ int   s_final;
    __shared__ float s_exact[MAXCAND];
    __shared__ float sx[DD];
    __shared__ float scs[MAXCAND][DD];
    if (lane == 0) swm[warp] = m;
    __syncthreads();
    float bv = swm[0];
#pragma unroll
    for (int w = 1; w < 8; ++w) bv = fmaxf(bv, swm[w]);

    // --- index of first occurrence + near-tie count ---
    int myidx = 0x7FFFFFFF;
    int cnt = 0;
    const float thr = bv - MARGIN;
#pragma unroll
    for (int e = 0; e < 8; ++e) {
        int g = (e < 4) ? tid * 4 + e : (tid + 256) * 4 + (e - 4);
        if (v[e] == bv) myidx = min(myidx, g);
        cnt += (v[e] > thr) ? 1 : 0;
    }
#pragma unroll
    for (int off = 16; off > 0; off >>= 1) {
        myidx = min(myidx, __shfl_xor_sync(0xFFFFFFFFu, myidx, off));
        cnt  +=            __shfl_xor_sync(0xFFFFFFFFu, cnt,  off);
    }
    if (lane == 0) { swi[warp] = myidx; swc[warp] = cnt; }
    __syncthreads();
    int bidx = swi[0], bcnt = swc[0];
#pragma unroll
    for (int w = 1; w < 8; ++w) { bidx = min(bidx, swi[w]); bcnt += swc[w]; }

    int final_idx = bidx;

    if (bcnt > 1) {
        // --- deterministic ascending-index candidate collection (<= 8) ---
        int cand[MAXCAND];
        int ccount = 0;
        int last = -1;
#pragma unroll 1
        for (int c = 0; c < MAXCAND; ++c) {
            int my = 0x7FFFFFFF;
#pragma unroll
            for (int e = 0; e < 8; ++e) {
                int g = (e < 4) ? tid * 4 + e : (tid + 256) * 4 + (e - 4);
                if (v[e] > thr && g > last) my = min(my, g);
            }
#pragma unroll
            for (int off = 16; off > 0; off >>= 1)
                my = min(my, __shfl_xor_sync(0xFFFFFFFFu, my, off));
            __syncthreads();
            if (lane == 0) swi[warp] = my;
            __syncthreads();
            int fnd = swi[0];
#pragma unroll
            for (int w = 1; w < 8; ++w) fnd = min(fnd, swi[w]);
            if (fnd == 0x7FFFFFFF) break;
            cand[ccount++] = fnd;    // uniform across block
            last = fnd;
        }

        // --- cooperative preload of x row + candidate cb rows ---
        for (int d = tid; d < DD; d += 256) {
            sx[d] = x[(size_t)n * DD + d];
            for (int c = 0; c < ccount; ++c)
                scs[c][d] = cb[(size_t)cand[c] * DD + d];
        }
        __syncthreads();

        // --- exact sequential-fp32 chain per candidate (bitwise-faithful) ---
        if (tid < ccount) {
            const float* cr = scs[tid];
            float s = 0.0f;
#pragma unroll 8
            for (int d = 0; d < DD; ++d) s = fmaf(sx[d], cr[d], s);
            s_exact[tid] = s;
        }
        __syncthreads();
        if (tid == 0) {
            float bvv = s_exact[0];
            int bii = cand[0];
            for (int c = 1; c < ccount; ++c) {
                if (s_exact[c] > bvv) { bvv = s_exact[c]; bii = cand[c]; }
            }
            s_final = bii;
        }
        __syncthreads();
        final_idx = s_final;
    }

    const int lbl = final_idx;
    if (tid == 0) {
        if (labels_are_i64) ((long long*)labels)[n] = (long long)lbl;
        else                ((float*)labels)[n] = (float)lbl;
    }
    if (tid < 128) {
        float4 c = ((const float4*)(cb + (size_t)lbl * DD))[tid];
        ((float4*)(preds + (size_t)n * DD))[tid] = c;
    }
}

// ---------------------------------------------------------------------------
// Launch
// ---------------------------------------------------------------------------
extern "C" void kernel_launch(void* const* d_in, const int* in_sizes, int n_in,
                              void* d_out, int out_size)
{
    const float* x  = (const float*)d_in[0];   // [N, D]
    const float* cb = (const float*)d_in[1];   // [K, D]

    float* out = (float*)d_out;
    const size_t predsSz = (size_t)NN * DD;
    const size_t simsSz  = (size_t)NN * KK;

    size_t labelElems;
    int labels_are_i64;
    if ((size_t)(unsigned)out_size == predsSz + 2 * (size_t)NN + simsSz) {
        labelElems = 2 * (size_t)NN; labels_are_i64 = 1;
    } else {
        labelElems = (size_t)NN;     labels_are_i64 = 0;
    }

    float* preds  = out;
    void*  labels = (void*)(out + predsSz);
    float* sims   = out + predsSz + labelElems;

    static int attr_set = 0;
    if (!attr_set) {
        cudaFuncSetAttribute(gemm_f16x2_kernel,
                             cudaFuncAttributeMaxDynamicSharedMemorySize, SMEM_BYTES);
        attr_set = 1;
    }

    dim3 grid(KK / BN, NN / BM);   // (16, 1024)
    gemm_f16x2_kernel<<<grid, 256, SMEM_BYTES>>>(x, cb, sims);
    argmax_gather_kernel<<<NN, 256>>>(sims, cb, x, preds, labels, labels_are_i64);
}